// round 16
// baseline (speedup 1.0000x reference)
#include <cuda_runtime.h>
#include <cuda_bf16.h>
#include <math.h>
#include <stdint.h>

#define BB 2
#define TT 2048
#define DD 1024
#define HH 16
#define DH 64
#define NREL 7

// Scratch (static device globals — no allocation)
__device__ float g_pk[NREL*HH*DH];

// packed bf16 hi/lo planes (W [K][N], acts [M][K], all layout-preserving)
__device__ __nv_bfloat16 g_wq_h[DD*HH*DH], g_wq_l[DD*HH*DH];
__device__ __nv_bfloat16 g_wk_h[DD*HH*DH], g_wk_l[DD*HH*DH];
__device__ __nv_bfloat16 g_wv_h[DD*HH*DH], g_wv_l[DD*HH*DH];
__device__ __nv_bfloat16 g_wo_h[DD*HH*DH], g_wo_l[DD*HH*DH];
__device__ __nv_bfloat16 g_x_h[BB*TT*DD],  g_x_l[BB*TT*DD];   // query in
__device__ __nv_bfloat16 g_y_h[BB*TT*DD],  g_y_l[BB*TT*DD];   // key in
__device__ __nv_bfloat16 g_z_h[BB*TT*DD],  g_z_l[BB*TT*DD];   // value in
__device__ __nv_bfloat16 g_qp_h[BB*TT*DD], g_qp_l[BB*TT*DD];  // q proj planes
__device__ __nv_bfloat16 g_kp_h[BB*TT*DD], g_kp_l[BB*TT*DD];  // k proj planes
__device__ __nv_bfloat16 g_vp_h[BB*TT*DD], g_vp_l[BB*TT*DD];  // v proj planes
__device__ __nv_bfloat16 g_a_h[BB*TT*DD],  g_a_l[BB*TT*DD];   // attn out planes

// ---------------------------------------------------------------------------
// helpers
// ---------------------------------------------------------------------------
__device__ __forceinline__ void cp16s(uint32_t saddr, const void* gmem) {
    asm volatile("cp.async.ca.shared.global [%0], [%1], 16;\n" :: "r"(saddr), "l"(gmem));
}
__device__ __forceinline__ void cp_commit() {
    asm volatile("cp.async.commit_group;\n");
}
__device__ __forceinline__ void cp_wait2() {
    asm volatile("cp.async.wait_group 2;\n");
}
__device__ __forceinline__ void cp_wait1() {
    asm volatile("cp.async.wait_group 1;\n");
}
__device__ __forceinline__ void cp_wait0() {
    asm volatile("cp.async.wait_group 0;\n");
}

__device__ __forceinline__ void mma_bf16(float* c, const uint32_t* a,
                                         uint32_t b0, uint32_t b1) {
    asm volatile(
        "mma.sync.aligned.m16n8k16.row.col.f32.bf16.bf16.f32 "
        "{%0,%1,%2,%3}, {%4,%5,%6,%7}, {%8,%9}, {%0,%1,%2,%3};"
        : "+f"(c[0]), "+f"(c[1]), "+f"(c[2]), "+f"(c[3])
        : "r"(a[0]), "r"(a[1]), "r"(a[2]), "r"(a[3]), "r"(b0), "r"(b1));
}

__device__ __forceinline__ void ldsm_x2_t(uint32_t& r0, uint32_t& r1, uint32_t addr) {
    asm volatile("ldmatrix.sync.aligned.m8n8.x2.trans.shared.b16 {%0,%1}, [%2];"
                 : "=r"(r0), "=r"(r1) : "r"(addr));
}
__device__ __forceinline__ void ldsm_x4(uint32_t* r, uint32_t addr) {
    asm volatile("ldmatrix.sync.aligned.m8n8.x4.shared.b16 {%0,%1,%2,%3}, [%4];"
                 : "=r"(r[0]), "=r"(r[1]), "=r"(r[2]), "=r"(r[3]) : "r"(addr));
}

__device__ __forceinline__ void split2_bf16(float x0, float x1,
                                            uint32_t& hi, uint32_t& lo) {
    __nv_bfloat16 h0 = __float2bfloat16_rn(x0);
    __nv_bfloat16 h1 = __float2bfloat16_rn(x1);
    float r0 = x0 - __bfloat162float(h0);
    float r1 = x1 - __bfloat162float(h1);
    __nv_bfloat162 H = __halves2bfloat162(h0, h1);
    __nv_bfloat162 L = __halves2bfloat162(__float2bfloat16_rn(r0),
                                          __float2bfloat16_rn(r1));
    hi = *(uint32_t*)&H;
    lo = *(uint32_t*)&L;
}

// ---------------------------------------------------------------------------
// pack fp32 -> bf16 hi/lo planes (layout preserved)
// ---------------------------------------------------------------------------
__global__ __launch_bounds__(256) void pack_bf16(
    const float* __restrict__ src, __nv_bfloat16* __restrict__ hi,
    __nv_bfloat16* __restrict__ lo, int n4)
{
    int i = blockIdx.x * 256 + threadIdx.x;
    if (i < n4) {
        float4 v = ((const float4*)src)[i];
        uint32_t h01, l01, h23, l23;
        split2_bf16(v.x, v.y, h01, l01);
        split2_bf16(v.z, v.w, h23, l23);
        ((uint2*)hi)[i] = make_uint2(h01, h23);
        ((uint2*)lo)[i] = make_uint2(l01, l23);
    }
}

// ---------------------------------------------------------------------------
// packed-bf16 3-term mma GEMM: C = A@W + bias (proven R12/R15 version).
// ---------------------------------------------------------------------------
#define AP2 40
#define BP2 136
#define A_PLANE2 (128 * AP2 * 2)
#define B_PLANE2 (32 * BP2 * 2)
#define STAGE2   (2 * A_PLANE2 + 2 * B_PLANE2)
#define G2_SMEM  (2 * STAGE2)

__global__ __launch_bounds__(256, 2) void gemm_bf16p2(
    const __nv_bfloat16* __restrict__ Ah_g, const __nv_bfloat16* __restrict__ Al_g,
    const __nv_bfloat16* __restrict__ Bh_g, const __nv_bfloat16* __restrict__ Bl_g,
    const float* __restrict__ bias, float* __restrict__ C,
    __nv_bfloat16* __restrict__ outh, __nv_bfloat16* __restrict__ outl,
    int M, int N, int K)
{
    extern __shared__ char smraw[];
    const uint32_t sb0 = (uint32_t)__cvta_generic_to_shared(smraw);

    const int tid  = threadIdx.x;
    const int warp = tid >> 5;
    const int lane = tid & 31;
    const int t    = lane & 3;
    const int g    = lane >> 2;
    const int lm   = lane & 15;
    const int lq   = lane >> 4;
    const int wm   = (warp & 3) * 32;
    const int wn   = (warp >> 2) * 64;
    const int bm   = blockIdx.y * 128;
    const int bn   = blockIdx.x * 128;
    const int NIT  = K >> 5;

    auto fill = [&](int c, int s) {
        const int k0 = c * 32;
        const uint32_t st = sb0 + s * STAGE2;
        #pragma unroll
        for (int u = 0; u < 8; u++) {
            int id = tid + u * 256;
            int plane = id >> 9;
            int wi = id & 511;
            if (plane < 2) {
                int row = wi >> 2;
                int c8  = (wi & 3) * 8;
                const __nv_bfloat16* src = (plane == 0) ? Ah_g : Al_g;
                uint32_t dst = st + plane * A_PLANE2 +
                               (uint32_t)(row * AP2 + c8) * 2;
                cp16s(dst, src + (size_t)(bm + row) * K + k0 + c8);
            } else {
                int krow = wi >> 4;
                int c8   = (wi & 15) * 8;
                const __nv_bfloat16* src = (plane == 2) ? Bh_g : Bl_g;
                uint32_t dst = st + 2 * A_PLANE2 + (plane - 2) * B_PLANE2 +
                               (uint32_t)(krow * BP2 + c8) * 2;
                cp16s(dst, src + (size_t)(k0 + krow) * N + bn + c8);
            }
        }
        cp_commit();
    };

    fill(0, 0);
    fill(1, 1);

    float acc[2][8][4];
    #pragma unroll
    for (int i = 0; i < 2; i++)
        #pragma unroll
        for (int j = 0; j < 8; j++)
            #pragma unroll
            for (int r = 0; r < 4; r++) acc[i][j][r] = 0.f;

    for (int it = 0; it < NIT; it++) {
        const int s = it & 1;
        if (it + 2 < NIT) cp_wait1(); else cp_wait0();
        __syncthreads();

        const uint32_t st = sb0 + s * STAGE2;
        const uint32_t ah_base = st;
        const uint32_t al_base = st + A_PLANE2;
        const uint32_t bh_base = st + 2 * A_PLANE2;
        const uint32_t bl_base = st + 2 * A_PLANE2 + B_PLANE2;

        #pragma unroll
        for (int ks = 0; ks < 2; ks++) {
            uint32_t ah[2][4], al[2][4];
            #pragma unroll
            for (int i = 0; i < 2; i++) {
                uint32_t off = (uint32_t)((wm + i * 16 + lm) * AP2) * 2 +
                               lq * 16 + ks * 32;
                ldsm_x4(ah[i], ah_base + off);
                ldsm_x4(al[i], al_base + off);
            }
            #pragma unroll
            for (int j = 0; j < 8; j++) {
                uint32_t boff = (uint32_t)((ks * 16 + lm) * BP2) * 2 +
                                (uint32_t)(wn + j * 8) * 2;
                uint32_t bh0, bh1, bl0, bl1;
                ldsm_x2_t(bh0, bh1, bh_base + boff);
                ldsm_x2_t(bl0, bl1, bl_base + boff);
                #pragma unroll
                for (int i = 0; i < 2; i++) {
                    mma_bf16(acc[i][j], ah[i], bh0, bh1);
                    mma_bf16(acc[i][j], ah[i], bl0, bl1);
                    mma_bf16(acc[i][j], al[i], bh0, bh1);
                }
            }
        }
        __syncthreads();
        if (it + 2 < NIT) fill(it + 2, s);
    }

    // epilogue
    #pragma unroll
    for (int j = 0; j < 8; j++) {
        const int col = bn + wn + j * 8 + 2 * t;
        const float bv0 = bias[col];
        const float bv1 = bias[col + 1];
        #pragma unroll
        for (int i = 0; i < 2; i++) {
            const int row0 = bm + wm + i * 16 + g;
            float a0 = acc[i][j][0] + bv0, a1 = acc[i][j][1] + bv1;
            float a2 = acc[i][j][2] + bv0, a3 = acc[i][j][3] + bv1;
            if (C) {
                *(float2*)(C + (size_t)row0 * N + col)       = make_float2(a0, a1);
                *(float2*)(C + (size_t)(row0 + 8) * N + col) = make_float2(a2, a3);
            } else {
                uint32_t h0, l0, h1, l1;
                split2_bf16(a0, a1, h0, l0);
                split2_bf16(a2, a3, h1, l1);
                *(uint32_t*)&outh[(size_t)row0 * N + col]       = h0;
                *(uint32_t*)&outl[(size_t)row0 * N + col]       = l0;
                *(uint32_t*)&outh[(size_t)(row0 + 8) * N + col] = h1;
                *(uint32_t*)&outl[(size_t)(row0 + 8) * N + col] = l1;
            }
        }
    }
}

// ---------------------------------------------------------------------------
// pk path
// ---------------------------------------------------------------------------
__global__ void pk_init(const float* __restrict__ bk, float* __restrict__ pk)
{
    int i = blockIdx.x * 256 + threadIdx.x;
    if (i < NREL * DD) pk[i] = bk[i & (DD - 1)];
}

__global__ __launch_bounds__(256) void pk_gemm_split(
    const float* __restrict__ pos_emb, const float* __restrict__ Wk,
    float* __restrict__ pk)
{
    __shared__ float pe_s[NREL][64];
    const int n  = blockIdx.x * 256 + threadIdx.x;
    const int k0 = blockIdx.y * 64;

    for (int i = threadIdx.x; i < NREL * 64; i += 256) {
        int r = i >> 6, kk = i & 63;
        pe_s[r][kk] = pos_emb[r * DD + k0 + kk];
    }
    __syncthreads();

    float acc[NREL];
    #pragma unroll
    for (int r = 0; r < NREL; r++) acc[r] = 0.f;

    #pragma unroll 4
    for (int kk = 0; kk < 64; kk++) {
        float w = Wk[(size_t)(k0 + kk) * DD + n];
        #pragma unroll
        for (int r = 0; r < NREL; r++) acc[r] += pe_s[r][kk] * w;
    }
    #pragma unroll
    for (int r = 0; r < NREL; r++)
        atomicAdd(&pk[r * DD + n], acc[r]);
}

// ---------------------------------------------------------------------------
// Flash attention: 128 query rows / CTA, 256 threads (8 warps x 16 rows).
// All operands pre-packed bf16 hi/lo planes; KV traffic halved vs 64-row tile.
// ---------------------------------------------------------------------------
#define KSTR 72
#define KVTILE_B (64 * KSTR * 2)       // 9216 per KV plane
#define QTILE_B  (128 * KSTR * 2)      // 18432 per Q plane

#define ATQ_H    0
#define ATQ_L    QTILE_B
#define ATKV     (2 * QTILE_B)         // 36864
#define KV_STAGE (4 * KVTILE_B)        // 36864
#define SMALL_OFF (ATKV + 2 * KV_STAGE)        // 110592
#define PKS_OFF  (SMALL_OFF + 128*8*4)         // +4096
#define US_OFF   (PKS_OFF + NREL*64*4)         // +1792
#define UK_OFF   (US_OFF + 64*4)
#define CORR_OFF (UK_OFF + 64*4)
#define AT_SMEM  (CORR_OFF + 32)               // ~117 KB -> 1 CTA/SM

__global__ __launch_bounds__(256, 1) void attn_mma(
    const __nv_bfloat16* __restrict__ qph, const __nv_bfloat16* __restrict__ qpl,
    const __nv_bfloat16* __restrict__ kph, const __nv_bfloat16* __restrict__ kpl,
    const __nv_bfloat16* __restrict__ vph, const __nv_bfloat16* __restrict__ vpl,
    const float* __restrict__ pk,
    const float* __restrict__ cbias, const float* __restrict__ rbias,
    __nv_bfloat16* __restrict__ outh, __nv_bfloat16* __restrict__ outl)
{
    extern __shared__ char smraw[];
    const uint32_t smb = (uint32_t)__cvta_generic_to_shared(smraw);
    __nv_bfloat16* Qh = (__nv_bfloat16*)(smraw + ATQ_H);
    __nv_bfloat16* Ql = (__nv_bfloat16*)(smraw + ATQ_L);
    float* smalls = (float*)(smraw + SMALL_OFF);
    float* pks    = (float*)(smraw + PKS_OFF);
    float* us     = (float*)(smraw + US_OFF);
    float* uk     = (float*)(smraw + UK_OFF);
    float* corr   = (float*)(smraw + CORR_OFF);

    const int tid  = threadIdx.x;
    const int warp = tid >> 5;
    const int lane = tid & 31;
    const int g    = lane >> 2;
    const int t    = lane & 3;
    const int lm   = lane & 15;
    const int wm   = warp * 16;          // 8 warps x 16 rows = 128
    const int h    = blockIdx.y;
    const int b    = blockIdx.z;
    const int q0   = blockIdx.x * 128;
    const int NKT  = TT / 64;            // 32

    const size_t hoff = (size_t)h * DH;

    // K/V tile fill: 4 planes x 64 rows x 8 units = 2048 chunks, 8/thread
    auto fillKV = [&](int c, int s) {
        const int kt = c * 64;
        const uint32_t st = smb + ATKV + s * KV_STAGE;
        #pragma unroll
        for (int u = 0; u < 8; u++) {
            int id = tid + u * 256;
            int plane = id >> 9;        // 0:Kh 1:Kl 2:Vh 3:Vl
            int wi = id & 511;
            int row = wi >> 3;
            int unit = wi & 7;
            const __nv_bfloat16* src =
                (plane == 0) ? kph : (plane == 1) ? kpl :
                (plane == 2) ? vph : vpl;
            uint32_t dst = st + plane * KVTILE_B +
                           (uint32_t)(row * (KSTR * 2) + unit * 16);
            cp16s(dst, src + ((size_t)b * TT + kt + row) * (HH * DH) + hoff + unit * 8);
        }
        cp_commit();
    };

    // Q fill (once): 2 planes x 128 rows x 8 units = 2048 chunks, 8/thread
    #pragma unroll
    for (int u = 0; u < 8; u++) {
        int id = tid + u * 256;
        int plane = id >> 10;
        int wi = id & 1023;
        int row = wi >> 3;
        int unit = wi & 7;
        const __nv_bfloat16* src = plane ? qpl : qph;
        uint32_t dst = smb + (plane ? ATQ_L : ATQ_H) +
                       (uint32_t)(row * (KSTR * 2) + unit * 16);
        cp16s(dst, src + ((size_t)b * TT + q0 + row) * (HH * DH) + hoff + unit * 8);
    }
    cp_commit();
    fillKV(0, 0);
    fillKV(1, 1);

    // biases / pk tiles
    if (tid < 64) us[tid] = cbias[h * DH + tid];
    for (int i = tid; i < NREL * 64; i += 256) {
        int r = i >> 6, d = i & 63;
        pks[i] = pk[r * DD + h * DH + d];
    }
    __syncthreads();

    if (tid < NREL) {
        float s = 0.f;
        for (int d = 0; d < 64; d++)
            s += rbias[h * DH + d] * pks[tid * 64 + d];
        corr[tid] = s;
    }

    cp_wait2();          // Q group complete
    __syncthreads();

    // smalls[row][r] = q_row . pk_r + rbias . pk_r
    if (tid < 128) {
        float accr[NREL];
        #pragma unroll
        for (int r = 0; r < NREL; r++) accr[r] = corr[r];
        for (int d = 0; d < 64; d++) {
            float qv = __bfloat162float(Qh[tid * KSTR + d]) +
                       __bfloat162float(Ql[tid * KSTR + d]);
            #pragma unroll
            for (int r = 0; r < NREL; r++) accr[r] += qv * pks[r * 64 + d];
        }
        #pragma unroll
        for (int r = 0; r < NREL; r++) smalls[tid * 8 + r] = accr[r];
    }

    // persistent Q fragments (per warp: rows wm..wm+15)
    uint32_t qfh[4][4], qfl[4][4];
    #pragma unroll
    for (int ks = 0; ks < 4; ks++) {
        int d0 = 16 * ks + 2 * t;
        qfh[ks][0] = *(uint32_t*)&Qh[(wm + g) * KSTR + d0];
        qfh[ks][1] = *(uint32_t*)&Qh[(wm + g + 8) * KSTR + d0];
        qfh[ks][2] = *(uint32_t*)&Qh[(wm + g) * KSTR + d0 + 8];
        qfh[ks][3] = *(uint32_t*)&Qh[(wm + g + 8) * KSTR + d0 + 8];
        qfl[ks][0] = *(uint32_t*)&Ql[(wm + g) * KSTR + d0];
        qfl[ks][1] = *(uint32_t*)&Ql[(wm + g + 8) * KSTR + d0];
        qfl[ks][2] = *(uint32_t*)&Ql[(wm + g) * KSTR + d0 + 8];
        qfl[ks][3] = *(uint32_t*)&Ql[(wm + g + 8) * KSTR + d0 + 8];
    }

    float m0 = -1e30f, m1 = -1e30f, l0 = 0.f, l1 = 0.f;
    float O[8][4];
    #pragma unroll
    for (int jd = 0; jd < 8; jd++)
        #pragma unroll
        for (int r = 0; r < 4; r++) O[jd][r] = 0.f;

    const float scale = 0.125f;
    const int tq0 = q0 + wm + g;
    const int rl0 = wm + g;

    for (int it = 0; it < NKT; it++) {
        const int s = it & 1;
        if (it + 1 < NKT) cp_wait1(); else cp_wait0();
        __syncthreads();

        const uint32_t kvb = smb + ATKV + s * KV_STAGE;
        const __nv_bfloat16* Khs = (__nv_bfloat16*)(smraw + ATKV + s * KV_STAGE);
        const __nv_bfloat16* Kls = Khs + KVTILE_B / 2;

        // uk[key] = u . (Kh+Kl)[key]; 4 threads per key (16 dims each)
        {
            int key = tid >> 2;
            int quar = tid & 3;
            float sum = 0.f;
            #pragma unroll
            for (int d2 = 0; d2 < 8; d2++) {
                int d = quar * 16 + d2 * 2;
                __nv_bfloat162 a = *(__nv_bfloat162*)&Khs[key * KSTR + d];
                __nv_bfloat162 bl = *(__nv_bfloat162*)&Kls[key * KSTR + d];
                float k0 = __bfloat162float(a.x) + __bfloat162float(bl.x);
                float k1 = __bfloat162float(a.y) + __bfloat162float(bl.y);
                sum += us[d] * k0 + us[d + 1] * k1;
            }
            sum += __shfl_xor_sync(0xffffffffu, sum, 1);
            sum += __shfl_xor_sync(0xffffffffu, sum, 2);
            if (!quar) uk[key] = sum;
        }

        // S = q K^T (3-term)
        float S[8][4];
        #pragma unroll
        for (int j = 0; j < 8; j++)
            #pragma unroll
            for (int r = 0; r < 4; r++) S[j][r] = 0.f;

        #pragma unroll
        for (int ks = 0; ks < 4; ks++) {
            const int d0 = 16 * ks + 2 * t;
            #pragma unroll
            for (int j = 0; j < 8; j++) {
                const int key = 8 * j + g;
                uint32_t bh0 = *(uint32_t*)&Khs[key * KSTR + d0];
                uint32_t bh1 = *(uint32_t*)&Khs[key * KSTR + d0 + 8];
                uint32_t bl0 = *(uint32_t*)&Kls[key * KSTR + d0];
                uint32_t bl1 = *(uint32_t*)&Kls[key * KSTR + d0 + 8];
                mma_bf16(S[j], qfh[ks], bh0, bh1);
                mma_bf16(S[j], qfh[ks], bl0, bl1);
                mma_bf16(S[j], qfl[ks], bh0, bh1);
            }
        }

        __syncthreads();          // uk visible to all warps

        // bias + scale + row max
        const int kt = it * 64;
        float mx0 = -1e30f, mx1 = -1e30f;
        #pragma unroll
        for (int j = 0; j < 8; j++) {
            #pragma unroll
            for (int c = 0; c < 2; c++) {
                int kk = 8 * j + 2 * t + c;
                int tk = kt + kk;
                int d0 = min(3, max(-3, tq0 - tk)) + 3;
                int d1 = min(3, max(-3, tq0 + 8 - tk)) + 3;
                float ukv = uk[kk];
                S[j][c]     = (S[j][c]     + ukv + smalls[rl0 * 8 + d0]) * scale;
                S[j][2 + c] = (S[j][2 + c] + ukv + smalls[(rl0 + 8) * 8 + d1]) * scale;
                mx0 = fmaxf(mx0, S[j][c]);
                mx1 = fmaxf(mx1, S[j][2 + c]);
            }
        }
        mx0 = fmaxf(mx0, __shfl_xor_sync(0xffffffffu, mx0, 1));
        mx0 = fmaxf(mx0, __shfl_xor_sync(0xffffffffu, mx0, 2));
        mx1 = fmaxf(mx1, __shfl_xor_sync(0xffffffffu, mx1, 1));
        mx1 = fmaxf(mx1, __shfl_xor_sync(0xffffffffu, mx1, 2));

        float mn0 = fmaxf(m0, mx0), mn1 = fmaxf(m1, mx1);
        float cr0 = __expf(m0 - mn0), cr1 = __expf(m1 - mn1);
        m0 = mn0; m1 = mn1;

        uint32_t phA[8], plA[8], phB[8], plB[8];
        float s0 = 0.f, s1 = 0.f;
        #pragma unroll
        for (int j = 0; j < 8; j++) {
            float p0 = __expf(S[j][0] - mn0);
            float p1 = __expf(S[j][1] - mn0);
            float p2 = __expf(S[j][2] - mn1);
            float p3 = __expf(S[j][3] - mn1);
            s0 += p0 + p1; s1 += p2 + p3;
            split2_bf16(p0, p1, phA[j], plA[j]);
            split2_bf16(p2, p3, phB[j], plB[j]);
        }
        s0 += __shfl_xor_sync(0xffffffffu, s0, 1);
        s0 += __shfl_xor_sync(0xffffffffu, s0, 2);
        s1 += __shfl_xor_sync(0xffffffffu, s1, 1);
        s1 += __shfl_xor_sync(0xffffffffu, s1, 2);
        l0 = l0 * cr0 + s0;
        l1 = l1 * cr1 + s1;

        #pragma unroll
        for (int jd = 0; jd < 8; jd++) {
            O[jd][0] *= cr0; O[jd][1] *= cr0;
            O[jd][2] *= cr1; O[jd][3] *= cr1;
        }

        // O += P V (3-term), V via ldmatrix.trans
        const uint32_t vh_lane = kvb + 2 * KVTILE_B + (uint32_t)lm * (KSTR * 2);
        const uint32_t vl_lane = kvb + 3 * KVTILE_B + (uint32_t)lm * (KSTR * 2);
        #pragma unroll
        for (int kv = 0; kv < 4; kv++) {
            uint32_t ah[4] = { phA[2*kv], phB[2*kv], phA[2*kv+1], phB[2*kv+1] };
            uint32_t al[4] = { plA[2*kv], plB[2*kv], plA[2*kv+1], plB[2*kv+1] };
            const uint32_t rh = vh_lane + (uint32_t)kv * 16 * (KSTR * 2);
            const uint32_t rl = vl_lane + (uint32_t)kv * 16 * (KSTR * 2);
            #pragma unroll
            for (int jd = 0; jd < 8; jd++) {
                uint32_t bh0, bh1, bl0, bl1;
                ldsm_x2_t(bh0, bh1, rh + jd * 16);
                ldsm_x2_t(bl0, bl1, rl + jd * 16);
                mma_bf16(O[jd], ah, bh0, bh1);
                mma_bf16(O[jd], ah, bl0, bl1);
                mma_bf16(O[jd], al, bh0, bh1);
            }
        }

        // all reads of stage s complete CTA-wide before cp.async overwrites it
        __syncthreads();
        if (it + 2 < NKT) fillKV(it + 2, s);
    }

    // epilogue: write bf16 hi/lo planes
    float inv0 = 1.f / l0, inv1 = 1.f / l1;
    const size_t r0 = (size_t)b * TT + tq0;
    const size_t r1 = r0 + 8;
    #pragma unroll
    for (int jd = 0; jd < 8; jd++) {
        int col = h * DH + 8 * jd + 2 * t;
        uint32_t hA, lA, hB, lB;
        split2_bf16(O[jd][0] * inv0, O[jd][1] * inv0, hA, lA);
        split2_bf16(O[jd][2] * inv1, O[jd][3] * inv1, hB, lB);
        *(uint32_t*)&outh[r0 * (HH * DH) + col] = hA;
        *(uint32_t*)&outl[r0 * (HH * DH) + col] = lA;
        *(uint32_t*)&outh[r1 * (HH * DH) + col] = hB;
        *(uint32_t*)&outl[r1 * (HH * DH) + col] = lB;
    }
}

// ---------------------------------------------------------------------------
extern "C" void kernel_launch(void* const* d_in, const int* in_sizes, int n_in,
                              void* d_out, int out_size)
{
    const float* query   = (const float*)d_in[0];
    const float* key_    = (const float*)d_in[1];
    const float* value   = (const float*)d_in[2];
    const float* Wq      = (const float*)d_in[3];
    const float* bq      = (const float*)d_in[4];
    const float* Wk      = (const float*)d_in[5];
    const float* bk      = (const float*)d_in[6];
    const float* Wv      = (const float*)d_in[7];
    const float* bv      = (const float*)d_in[8];
    const float* Wo      = (const float*)d_in[9];
    const float* bo      = (const float*)d_in[10];
    const float* cbias   = (const float*)d_in[11];
    const float* rbias   = (const float*)d_in[12];
    const float* pos_emb = (const float*)d_in[13];

    float *pk;
    cudaGetSymbolAddress((void**)&pk, g_pk);

    __nv_bfloat16 *wqh, *wql, *wkh, *wkl, *wvh, *wvl, *woh, *wol;
    __nv_bfloat16 *xh, *xl, *yh, *yl, *zh, *zl, *ath, *atl;
    __nv_bfloat16 *qph, *qpl, *kp_h, *kp_l, *vp_h, *vp_l;
    cudaGetSymbolAddress((void**)&wqh, g_wq_h); cudaGetSymbolAddress((void**)&wql, g_wq_l);
    cudaGetSymbolAddress((void**)&wkh, g_wk_h); cudaGetSymbolAddress((void**)&wkl, g_wk_l);
    cudaGetSymbolAddress((void**)&wvh, g_wv_h); cudaGetSymbolAddress((void**)&wvl, g_wv_l);
    cudaGetSymbolAddress((void**)&woh, g_wo_h); cudaGetSymbolAddress((void**)&wol, g_wo_l);
    cudaGetSymbolAddress((void**)&xh, g_x_h);   cudaGetSymbolAddress((void**)&xl, g_x_l);
    cudaGetSymbolAddress((void**)&yh, g_y_h);   cudaGetSymbolAddress((void**)&yl, g_y_l);
    cudaGetSymbolAddress((void**)&zh, g_z_h);   cudaGetSymbolAddress((void**)&zl, g_z_l);
    cudaGetSymbolAddress((void**)&ath, g_a_h);  cudaGetSymbolAddress((void**)&atl, g_a_l);
    cudaGetSymbolAddress((void**)&qph, g_qp_h); cudaGetSymbolAddress((void**)&qpl, g_qp_l);
    cudaGetSymbolAddress((void**)&kp_h, g_kp_h); cudaGetSymbolAddress((void**)&kp_l, g_kp_l);
    cudaGetSymbolAddress((void**)&vp_h, g_vp_h); cudaGetSymbolAddress((void**)&vp_l, g_vp_l);

    const int M = BB * TT;     // 4096
    const int N = HH * DH;     // 1024
    const int K = DD;          // 1024

    const int wn4 = DD * HH * DH / 4;
    const int an4 = BB * TT * DD / 4;
    pack_bf16<<<wn4 / 256, 256>>>(Wq, wqh, wql, wn4);
    pack_bf16<<<wn4 / 256, 256>>>(Wk, wkh, wkl, wn4);
    pack_bf16<<<wn4 / 256, 256>>>(Wv, wvh, wvl, wn4);
    pack_bf16<<<wn4 / 256, 256>>>(Wo, woh, wol, wn4);
    pack_bf16<<<an4 / 256, 256>>>(query, xh, xl, an4);
    pack_bf16<<<an4 / 256, 256>>>(key_,  yh, yl, an4);
    pack_bf16<<<an4 / 256, 256>>>(value, zh, zl, an4);

    cudaFuncSetAttribute(gemm_bf16p2,
                         cudaFuncAttributeMaxDynamicSharedMemorySize, G2_SMEM);
    dim3 gg(N / 128, M / 128);  // (8, 32)
    gemm_bf16p2<<<gg, 256, G2_SMEM>>>(xh, xl, wqh, wql, bq,
                                      nullptr, qph, qpl, M, N, K);
    gemm_bf16p2<<<gg, 256, G2_SMEM>>>(yh, yl, wkh, wkl, bk,
                                      nullptr, kp_h, kp_l, M, N, K);
    gemm_bf16p2<<<gg, 256, G2_SMEM>>>(zh, zl, wvh, wvl, bv,
                                      nullptr, vp_h, vp_l, M, N, K);

    pk_init<<<(NREL * DD + 255) / 256, 256>>>(bk, pk);
    pk_gemm_split<<<dim3(DD / 256, DD / 64), 256>>>(pos_emb, Wk, pk);

    cudaFuncSetAttribute(attn_mma,
                         cudaFuncAttributeMaxDynamicSharedMemorySize, AT_SMEM);
    attn_mma<<<dim3(TT / 128, HH, BB), 256, AT_SMEM>>>(
        qph, qpl, kp_h, kp_l, vp_h, vp_l, pk, cbias, rbias, ath, atl);

    // output projection -> d_out
    gemm_bf16p2<<<gg, 256, G2_SMEM>>>(ath, atl, woh, wol, bo,
                                      (float*)d_out, nullptr, nullptr, M, N, K);
}

// round 17
// speedup vs baseline: 1.0252x; 1.0252x over previous
#include <cuda_runtime.h>
#include <cuda_bf16.h>
#include <math.h>
#include <stdint.h>

#define BB 2
#define TT 2048
#define DD 1024
#define HH 16
#define DH 64
#define NREL 7

// Scratch (static device globals — no allocation)
__device__ float g_pk[NREL*HH*DH];

// packed bf16 hi/lo planes (W [K][N], acts [M][K], all layout-preserving)
__device__ __nv_bfloat16 g_wq_h[DD*HH*DH], g_wq_l[DD*HH*DH];
__device__ __nv_bfloat16 g_wk_h[DD*HH*DH], g_wk_l[DD*HH*DH];
__device__ __nv_bfloat16 g_wv_h[DD*HH*DH], g_wv_l[DD*HH*DH];
__device__ __nv_bfloat16 g_wo_h[DD*HH*DH], g_wo_l[DD*HH*DH];
__device__ __nv_bfloat16 g_x_h[BB*TT*DD],  g_x_l[BB*TT*DD];   // query in
__device__ __nv_bfloat16 g_y_h[BB*TT*DD],  g_y_l[BB*TT*DD];   // key in
__device__ __nv_bfloat16 g_z_h[BB*TT*DD],  g_z_l[BB*TT*DD];   // value in
__device__ __nv_bfloat16 g_qp_h[BB*TT*DD], g_qp_l[BB*TT*DD];  // q proj planes
__device__ __nv_bfloat16 g_kp_h[BB*TT*DD], g_kp_l[BB*TT*DD];  // k proj planes
__device__ __nv_bfloat16 g_vp_h[BB*TT*DD], g_vp_l[BB*TT*DD];  // v proj planes
__device__ __nv_bfloat16 g_a_h[BB*TT*DD],  g_a_l[BB*TT*DD];   // attn out planes

// ---------------------------------------------------------------------------
// helpers
// ---------------------------------------------------------------------------
__device__ __forceinline__ void cp16s(uint32_t saddr, const void* gmem) {
    asm volatile("cp.async.ca.shared.global [%0], [%1], 16;\n" :: "r"(saddr), "l"(gmem));
}
__device__ __forceinline__ void cp_commit() {
    asm volatile("cp.async.commit_group;\n");
}
__device__ __forceinline__ void cp_wait2() {
    asm volatile("cp.async.wait_group 2;\n");
}
__device__ __forceinline__ void cp_wait1() {
    asm volatile("cp.async.wait_group 1;\n");
}
__device__ __forceinline__ void cp_wait0() {
    asm volatile("cp.async.wait_group 0;\n");
}

__device__ __forceinline__ void mma_bf16(float* c, const uint32_t* a,
                                         uint32_t b0, uint32_t b1) {
    asm volatile(
        "mma.sync.aligned.m16n8k16.row.col.f32.bf16.bf16.f32 "
        "{%0,%1,%2,%3}, {%4,%5,%6,%7}, {%8,%9}, {%0,%1,%2,%3};"
        : "+f"(c[0]), "+f"(c[1]), "+f"(c[2]), "+f"(c[3])
        : "r"(a[0]), "r"(a[1]), "r"(a[2]), "r"(a[3]), "r"(b0), "r"(b1));
}

__device__ __forceinline__ void ldsm_x2_t(uint32_t& r0, uint32_t& r1, uint32_t addr) {
    asm volatile("ldmatrix.sync.aligned.m8n8.x2.trans.shared.b16 {%0,%1}, [%2];"
                 : "=r"(r0), "=r"(r1) : "r"(addr));
}
__device__ __forceinline__ void ldsm_x4(uint32_t* r, uint32_t addr) {
    asm volatile("ldmatrix.sync.aligned.m8n8.x4.shared.b16 {%0,%1,%2,%3}, [%4];"
                 : "=r"(r[0]), "=r"(r[1]), "=r"(r[2]), "=r"(r[3]) : "r"(addr));
}

__device__ __forceinline__ void split2_bf16(float x0, float x1,
                                            uint32_t& hi, uint32_t& lo) {
    __nv_bfloat16 h0 = __float2bfloat16_rn(x0);
    __nv_bfloat16 h1 = __float2bfloat16_rn(x1);
    float r0 = x0 - __bfloat162float(h0);
    float r1 = x1 - __bfloat162float(h1);
    __nv_bfloat162 H = __halves2bfloat162(h0, h1);
    __nv_bfloat162 L = __halves2bfloat162(__float2bfloat16_rn(r0),
                                          __float2bfloat16_rn(r1));
    hi = *(uint32_t*)&H;
    lo = *(uint32_t*)&L;
}

// ---------------------------------------------------------------------------
// merged pack kernels: grid.y selects tensor
// ---------------------------------------------------------------------------
struct Pack4Args {
    const float* src[4];
    __nv_bfloat16* hi[4];
    __nv_bfloat16* lo[4];
};

__global__ __launch_bounds__(256) void pack_bf16_multi(
    Pack4Args args, int n4)
{
    int i = blockIdx.x * 256 + threadIdx.x;
    int z = blockIdx.y;
    if (i < n4) {
        float4 v = ((const float4*)args.src[z])[i];
        uint32_t h01, l01, h23, l23;
        split2_bf16(v.x, v.y, h01, l01);
        split2_bf16(v.z, v.w, h23, l23);
        ((uint2*)args.hi[z])[i] = make_uint2(h01, h23);
        ((uint2*)args.lo[z])[i] = make_uint2(l01, l23);
    }
}

// ---------------------------------------------------------------------------
// packed-bf16 3-term mma GEMM core (proven R12/R15 body).
// BM=128, BN=128, BK=32, 256 threads (8 warps = 4m x 2n), warp tile 32x64.
// ---------------------------------------------------------------------------
#define AP2 40
#define BP2 136
#define A_PLANE2 (128 * AP2 * 2)
#define B_PLANE2 (32 * BP2 * 2)
#define STAGE2   (2 * A_PLANE2 + 2 * B_PLANE2)
#define G2_SMEM  (2 * STAGE2)

__device__ __forceinline__ void gemm_core(
    const __nv_bfloat16* __restrict__ Ah_g, const __nv_bfloat16* __restrict__ Al_g,
    const __nv_bfloat16* __restrict__ Bh_g, const __nv_bfloat16* __restrict__ Bl_g,
    const float* __restrict__ bias, float* __restrict__ C,
    __nv_bfloat16* __restrict__ outh, __nv_bfloat16* __restrict__ outl,
    int M, int N, int K, char* smraw)
{
    const uint32_t sb0 = (uint32_t)__cvta_generic_to_shared(smraw);

    const int tid  = threadIdx.x;
    const int warp = tid >> 5;
    const int lane = tid & 31;
    const int t    = lane & 3;
    const int g    = lane >> 2;
    const int lm   = lane & 15;
    const int lq   = lane >> 4;
    const int wm   = (warp & 3) * 32;
    const int wn   = (warp >> 2) * 64;
    const int bm   = blockIdx.y * 128;
    const int bn   = blockIdx.x * 128;
    const int NIT  = K >> 5;

    auto fill = [&](int c, int s) {
        const int k0 = c * 32;
        const uint32_t st = sb0 + s * STAGE2;
        #pragma unroll
        for (int u = 0; u < 8; u++) {
            int id = tid + u * 256;
            int plane = id >> 9;
            int wi = id & 511;
            if (plane < 2) {
                int row = wi >> 2;
                int c8  = (wi & 3) * 8;
                const __nv_bfloat16* src = (plane == 0) ? Ah_g : Al_g;
                uint32_t dst = st + plane * A_PLANE2 +
                               (uint32_t)(row * AP2 + c8) * 2;
                cp16s(dst, src + (size_t)(bm + row) * K + k0 + c8);
            } else {
                int krow = wi >> 4;
                int c8   = (wi & 15) * 8;
                const __nv_bfloat16* src = (plane == 2) ? Bh_g : Bl_g;
                uint32_t dst = st + 2 * A_PLANE2 + (plane - 2) * B_PLANE2 +
                               (uint32_t)(krow * BP2 + c8) * 2;
                cp16s(dst, src + (size_t)(k0 + krow) * N + bn + c8);
            }
        }
        cp_commit();
    };

    fill(0, 0);
    fill(1, 1);

    float acc[2][8][4];
    #pragma unroll
    for (int i = 0; i < 2; i++)
        #pragma unroll
        for (int j = 0; j < 8; j++)
            #pragma unroll
            for (int r = 0; r < 4; r++) acc[i][j][r] = 0.f;

    for (int it = 0; it < NIT; it++) {
        const int s = it & 1;
        if (it + 2 < NIT) cp_wait1(); else cp_wait0();
        __syncthreads();

        const uint32_t st = sb0 + s * STAGE2;
        const uint32_t ah_base = st;
        const uint32_t al_base = st + A_PLANE2;
        const uint32_t bh_base = st + 2 * A_PLANE2;
        const uint32_t bl_base = st + 2 * A_PLANE2 + B_PLANE2;

        #pragma unroll
        for (int ks = 0; ks < 2; ks++) {
            uint32_t ah[2][4], al[2][4];
            #pragma unroll
            for (int i = 0; i < 2; i++) {
                uint32_t off = (uint32_t)((wm + i * 16 + lm) * AP2) * 2 +
                               lq * 16 + ks * 32;
                ldsm_x4(ah[i], ah_base + off);
                ldsm_x4(al[i], al_base + off);
            }
            #pragma unroll
            for (int j = 0; j < 8; j++) {
                uint32_t boff = (uint32_t)((ks * 16 + lm) * BP2) * 2 +
                                (uint32_t)(wn + j * 8) * 2;
                uint32_t bh0, bh1, bl0, bl1;
                ldsm_x2_t(bh0, bh1, bh_base + boff);
                ldsm_x2_t(bl0, bl1, bl_base + boff);
                #pragma unroll
                for (int i = 0; i < 2; i++) {
                    mma_bf16(acc[i][j], ah[i], bh0, bh1);
                    mma_bf16(acc[i][j], ah[i], bl0, bl1);
                    mma_bf16(acc[i][j], al[i], bh0, bh1);
                }
            }
        }
        __syncthreads();
        if (it + 2 < NIT) fill(it + 2, s);
    }

    // epilogue
    #pragma unroll
    for (int j = 0; j < 8; j++) {
        const int col = bn + wn + j * 8 + 2 * t;
        const float bv0 = bias[col];
        const float bv1 = bias[col + 1];
        #pragma unroll
        for (int i = 0; i < 2; i++) {
            const int row0 = bm + wm + i * 16 + g;
            float a0 = acc[i][j][0] + bv0, a1 = acc[i][j][1] + bv1;
            float a2 = acc[i][j][2] + bv0, a3 = acc[i][j][3] + bv1;
            if (C) {
                *(float2*)(C + (size_t)row0 * N + col)       = make_float2(a0, a1);
                *(float2*)(C + (size_t)(row0 + 8) * N + col) = make_float2(a2, a3);
            } else {
                uint32_t h0, l0, h1, l1;
                split2_bf16(a0, a1, h0, l0);
                split2_bf16(a2, a3, h1, l1);
                *(uint32_t*)&outh[(size_t)row0 * N + col]       = h0;
                *(uint32_t*)&outl[(size_t)row0 * N + col]       = l0;
                *(uint32_t*)&outh[(size_t)(row0 + 8) * N + col] = h1;
                *(uint32_t*)&outl[(size_t)(row0 + 8) * N + col] = l1;
            }
        }
    }
}

// merged QKV GEMM: grid.z selects which projection
struct QKVArgs {
    const __nv_bfloat16 *Ah[3], *Al[3], *Bh[3], *Bl[3];
    const float* bias[3];
    __nv_bfloat16 *oh[3], *ol[3];
};

__global__ __launch_bounds__(256, 2) void gemm_qkv(
    QKVArgs args, int M, int N, int K)
{
    extern __shared__ char smraw[];
    const int z = blockIdx.z;
    gemm_core(args.Ah[z], args.Al[z], args.Bh[z], args.Bl[z],
              args.bias[z], nullptr, args.oh[z], args.ol[z], M, N, K, smraw);
}

__global__ __launch_bounds__(256, 2) void gemm_out(
    const __nv_bfloat16* __restrict__ Ah_g, const __nv_bfloat16* __restrict__ Al_g,
    const __nv_bfloat16* __restrict__ Bh_g, const __nv_bfloat16* __restrict__ Bl_g,
    const float* __restrict__ bias, float* __restrict__ C,
    int M, int N, int K)
{
    extern __shared__ char smraw[];
    gemm_core(Ah_g, Al_g, Bh_g, Bl_g, bias, C, nullptr, nullptr, M, N, K, smraw);
}

// ---------------------------------------------------------------------------
// pk path
// ---------------------------------------------------------------------------
__global__ void pk_init(const float* __restrict__ bk, float* __restrict__ pk)
{
    int i = blockIdx.x * 256 + threadIdx.x;
    if (i < NREL * DD) pk[i] = bk[i & (DD - 1)];
}

__global__ __launch_bounds__(256) void pk_gemm_split(
    const float* __restrict__ pos_emb, const float* __restrict__ Wk,
    float* __restrict__ pk)
{
    __shared__ float pe_s[NREL][64];
    const int n  = blockIdx.x * 256 + threadIdx.x;
    const int k0 = blockIdx.y * 64;

    for (int i = threadIdx.x; i < NREL * 64; i += 256) {
        int r = i >> 6, kk = i & 63;
        pe_s[r][kk] = pos_emb[r * DD + k0 + kk];
    }
    __syncthreads();

    float acc[NREL];
    #pragma unroll
    for (int r = 0; r < NREL; r++) acc[r] = 0.f;

    #pragma unroll 4
    for (int kk = 0; kk < 64; kk++) {
        float w = Wk[(size_t)(k0 + kk) * DD + n];
        #pragma unroll
        for (int r = 0; r < NREL; r++) acc[r] += pe_s[r][kk] * w;
    }
    #pragma unroll
    for (int r = 0; r < NREL; r++)
        atomicAdd(&pk[r * DD + n], acc[r]);
}

// ---------------------------------------------------------------------------
// Flash attention (proven R15 version: 64 q-rows, 128 threads, 2 CTA/SM).
// ---------------------------------------------------------------------------
#define KSTR 72
#define TILE_B (64 * KSTR * 2)      // 9216

#define ATQ_H    0
#define ATQ_L    TILE_B
#define ATKV     (2 * TILE_B)       // 18432
#define KV_STAGE (4 * TILE_B)       // 36864
#define SMALL_OFF (ATKV + 2 * KV_STAGE)        // 92160
#define PKS_OFF  (SMALL_OFF + 64*8*4)
#define US_OFF   (PKS_OFF + NREL*64*4)
#define UK_OFF   (US_OFF + 64*4)
#define CORR_OFF (UK_OFF + 64*4)
#define AT_SMEM  (CORR_OFF + 32)

__global__ __launch_bounds__(128, 2) void attn_mma(
    const __nv_bfloat16* __restrict__ qph, const __nv_bfloat16* __restrict__ qpl,
    const __nv_bfloat16* __restrict__ kph, const __nv_bfloat16* __restrict__ kpl,
    const __nv_bfloat16* __restrict__ vph, const __nv_bfloat16* __restrict__ vpl,
    const float* __restrict__ pk,
    const float* __restrict__ cbias, const float* __restrict__ rbias,
    __nv_bfloat16* __restrict__ outh, __nv_bfloat16* __restrict__ outl)
{
    extern __shared__ char smraw[];
    const uint32_t smb = (uint32_t)__cvta_generic_to_shared(smraw);
    __nv_bfloat16* Qh = (__nv_bfloat16*)(smraw + ATQ_H);
    __nv_bfloat16* Ql = (__nv_bfloat16*)(smraw + ATQ_L);
    float* smalls = (float*)(smraw + SMALL_OFF);
    float* pks    = (float*)(smraw + PKS_OFF);
    float* us     = (float*)(smraw + US_OFF);
    float* uk     = (float*)(smraw + UK_OFF);
    float* corr   = (float*)(smraw + CORR_OFF);

    const int tid  = threadIdx.x;
    const int warp = tid >> 5;
    const int lane = tid & 31;
    const int g    = lane >> 2;
    const int t    = lane & 3;
    const int lm   = lane & 15;
    const int wm   = warp * 16;
    const int h    = blockIdx.y;
    const int b    = blockIdx.z;
    const int q0   = blockIdx.x * 64;
    const int NKT  = TT / 64;       // 32

    const size_t hoff = (size_t)h * DH;

    auto fillKV = [&](int c, int s) {
        const int kt = c * 64;
        const uint32_t st = smb + ATKV + s * KV_STAGE;
        #pragma unroll
        for (int u = 0; u < 16; u++) {
            int id = tid + u * 128;
            int plane = id >> 9;        // 0:Kh 1:Kl 2:Vh 3:Vl
            int wi = id & 511;
            int row = wi >> 3;
            int unit = wi & 7;
            const __nv_bfloat16* src =
                (plane == 0) ? kph : (plane == 1) ? kpl :
                (plane == 2) ? vph : vpl;
            uint32_t dst = st + plane * TILE_B +
                           (uint32_t)(row * (KSTR * 2) + unit * 16);
            cp16s(dst, src + ((size_t)b * TT + kt + row) * (HH * DH) + hoff + unit * 8);
        }
        cp_commit();
    };

    // Q fill (once)
    #pragma unroll
    for (int u = 0; u < 8; u++) {
        int id = tid + u * 128;
        int plane = id >> 9;
        int wi = id & 511;
        int row = wi >> 3;
        int unit = wi & 7;
        const __nv_bfloat16* src = plane ? qpl : qph;
        uint32_t dst = smb + (plane ? ATQ_L : ATQ_H) +
                       (uint32_t)(row * (KSTR * 2) + unit * 16);
        cp16s(dst, src + ((size_t)b * TT + q0 + row) * (HH * DH) + hoff + unit * 8);
    }
    cp_commit();
    fillKV(0, 0);
    fillKV(1, 1);

    if (tid < 64) us[tid] = cbias[h * DH + tid];
    for (int i = tid; i < NREL * 64; i += 128) {
        int r = i >> 6, d = i & 63;
        pks[i] = pk[r * DD + h * DH + d];
    }
    __syncthreads();

    if (tid < NREL) {
        float s = 0.f;
        for (int d = 0; d < 64; d++)
            s += rbias[h * DH + d] * pks[tid * 64 + d];
        corr[tid] = s;
    }

    cp_wait2();          // Q group complete
    __syncthreads();

    if (tid < 64) {
        float accr[NREL];
        #pragma unroll
        for (int r = 0; r < NREL; r++) accr[r] = corr[r];
        for (int d = 0; d < 64; d++) {
            float qv = __bfloat162float(Qh[tid * KSTR + d]) +
                       __bfloat162float(Ql[tid * KSTR + d]);
            #pragma unroll
            for (int r = 0; r < NREL; r++) accr[r] += qv * pks[r * 64 + d];
        }
        #pragma unroll
        for (int r = 0; r < NREL; r++) smalls[tid * 8 + r] = accr[r];
    }

    uint32_t qfh[4][4], qfl[4][4];
    #pragma unroll
    for (int ks = 0; ks < 4; ks++) {
        int d0 = 16 * ks + 2 * t;
        qfh[ks][0] = *(uint32_t*)&Qh[(wm + g) * KSTR + d0];
        qfh[ks][1] = *(uint32_t*)&Qh[(wm + g + 8) * KSTR + d0];
        qfh[ks][2] = *(uint32_t*)&Qh[(wm + g) * KSTR + d0 + 8];
        qfh[ks][3] = *(uint32_t*)&Qh[(wm + g + 8) * KSTR + d0 + 8];
        qfl[ks][0] = *(uint32_t*)&Ql[(wm + g) * KSTR + d0];
        qfl[ks][1] = *(uint32_t*)&Ql[(wm + g + 8) * KSTR + d0];
        qfl[ks][2] = *(uint32_t*)&Ql[(wm + g) * KSTR + d0 + 8];
        qfl[ks][3] = *(uint32_t*)&Ql[(wm + g + 8) * KSTR + d0 + 8];
    }

    float m0 = -1e30f, m1 = -1e30f, l0 = 0.f, l1 = 0.f;
    float O[8][4];
    #pragma unroll
    for (int jd = 0; jd < 8; jd++)
        #pragma unroll
        for (int r = 0; r < 4; r++) O[jd][r] = 0.f;

    const float scale = 0.125f;
    const int tq0 = q0 + wm + g;
    const int rl0 = wm + g;

    for (int it = 0; it < NKT; it++) {
        const int s = it & 1;
        if (it + 1 < NKT) cp_wait1(); else cp_wait0();
        __syncthreads();

        const uint32_t kvb = smb + ATKV + s * KV_STAGE;
        const __nv_bfloat16* Khs = (__nv_bfloat16*)(smraw + ATKV + s * KV_STAGE);
        const __nv_bfloat16* Kls = Khs + TILE_B / 2;

        // uk[key] = u . (Kh+Kl)[key]; 2 threads per key
        {
            int key = tid >> 1;
            int half = tid & 1;
            float sum = 0.f;
            #pragma unroll
            for (int d2 = 0; d2 < 16; d2++) {
                int d = half * 32 + d2 * 2;
                __nv_bfloat162 a = *(__nv_bfloat162*)&Khs[key * KSTR + d];
                __nv_bfloat162 bl = *(__nv_bfloat162*)&Kls[key * KSTR + d];
                float k0 = __bfloat162float(a.x) + __bfloat162float(bl.x);
                float k1 = __bfloat162float(a.y) + __bfloat162float(bl.y);
                sum += us[d] * k0 + us[d + 1] * k1;
            }
            sum += __shfl_xor_sync(0xffffffffu, sum, 1);
            if (!half) uk[key] = sum;
        }

        // S = q K^T (3-term)
        float S[8][4];
        #pragma unroll
        for (int j = 0; j < 8; j++)
            #pragma unroll
            for (int r = 0; r < 4; r++) S[j][r] = 0.f;

        #pragma unroll
        for (int ks = 0; ks < 4; ks++) {
            const int d0 = 16 * ks + 2 * t;
            #pragma unroll
            for (int j = 0; j < 8; j++) {
                const int key = 8 * j + g;
                uint32_t bh0 = *(uint32_t*)&Khs[key * KSTR + d0];
                uint32_t bh1 = *(uint32_t*)&Khs[key * KSTR + d0 + 8];
                uint32_t bl0 = *(uint32_t*)&Kls[key * KSTR + d0];
                uint32_t bl1 = *(uint32_t*)&Kls[key * KSTR + d0 + 8];
                mma_bf16(S[j], qfh[ks], bh0, bh1);
                mma_bf16(S[j], qfh[ks], bl0, bl1);
                mma_bf16(S[j], qfl[ks], bh0, bh1);
            }
        }

        __syncthreads();          // uk visible to all warps

        const int kt = it * 64;
        float mx0 = -1e30f, mx1 = -1e30f;
        #pragma unroll
        for (int j = 0; j < 8; j++) {
            #pragma unroll
            for (int c = 0; c < 2; c++) {
                int kk = 8 * j + 2 * t + c;
                int tk = kt + kk;
                int d0 = min(3, max(-3, tq0 - tk)) + 3;
                int d1 = min(3, max(-3, tq0 + 8 - tk)) + 3;
                float ukv = uk[kk];
                S[j][c]     = (S[j][c]     + ukv + smalls[rl0 * 8 + d0]) * scale;
                S[j][2 + c] = (S[j][2 + c] + ukv + smalls[(rl0 + 8) * 8 + d1]) * scale;
                mx0 = fmaxf(mx0, S[j][c]);
                mx1 = fmaxf(mx1, S[j][2 + c]);
            }
        }
        mx0 = fmaxf(mx0, __shfl_xor_sync(0xffffffffu, mx0, 1));
        mx0 = fmaxf(mx0, __shfl_xor_sync(0xffffffffu, mx0, 2));
        mx1 = fmaxf(mx1, __shfl_xor_sync(0xffffffffu, mx1, 1));
        mx1 = fmaxf(mx1, __shfl_xor_sync(0xffffffffu, mx1, 2));

        float mn0 = fmaxf(m0, mx0), mn1 = fmaxf(m1, mx1);
        float cr0 = __expf(m0 - mn0), cr1 = __expf(m1 - mn1);
        m0 = mn0; m1 = mn1;

        uint32_t phA[8], plA[8], phB[8], plB[8];
        float s0 = 0.f, s1 = 0.f;
        #pragma unroll
        for (int j = 0; j < 8; j++) {
            float p0 = __expf(S[j][0] - mn0);
            float p1 = __expf(S[j][1] - mn0);
            float p2 = __expf(S[j][2] - mn1);
            float p3 = __expf(S[j][3] - mn1);
            s0 += p0 + p1; s1 += p2 + p3;
            split2_bf16(p0, p1, phA[j], plA[j]);
            split2_bf16(p2, p3, phB[j], plB[j]);
        }
        s0 += __shfl_xor_sync(0xffffffffu, s0, 1);
        s0 += __shfl_xor_sync(0xffffffffu, s0, 2);
        s1 += __shfl_xor_sync(0xffffffffu, s1, 1);
        s1 += __shfl_xor_sync(0xffffffffu, s1, 2);
        l0 = l0 * cr0 + s0;
        l1 = l1 * cr1 + s1;

        #pragma unroll
        for (int jd = 0; jd < 8; jd++) {
            O[jd][0] *= cr0; O[jd][1] *= cr0;
            O[jd][2] *= cr1; O[jd][3] *= cr1;
        }

        const uint32_t vh_lane = kvb + 2 * TILE_B + (uint32_t)lm * (KSTR * 2);
        const uint32_t vl_lane = kvb + 3 * TILE_B + (uint32_t)lm * (KSTR * 2);
        #pragma unroll
        for (int kv = 0; kv < 4; kv++) {
            uint32_t ah[4] = { phA[2*kv], phB[2*kv], phA[2*kv+1], phB[2*kv+1] };
            uint32_t al[4] = { plA[2*kv], plB[2*kv], plA[2*kv+1], plB[2*kv+1] };
            const uint32_t rh = vh_lane + (uint32_t)kv * 16 * (KSTR * 2);
            const uint32_t rl = vl_lane + (uint32_t)kv * 16 * (KSTR * 2);
            #pragma unroll
            for (int jd = 0; jd < 8; jd++) {
                uint32_t bh0, bh1, bl0, bl1;
                ldsm_x2_t(bh0, bh1, rh + jd * 16);
                ldsm_x2_t(bl0, bl1, rl + jd * 16);
                mma_bf16(O[jd], ah, bh0, bh1);
                mma_bf16(O[jd], ah, bl0, bl1);
                mma_bf16(O[jd], al, bh0, bh1);
            }
        }

        // all reads of stage s complete CTA-wide before cp.async overwrites it
        __syncthreads();
        if (it + 2 < NKT) fillKV(it + 2, s);
    }

    // epilogue: write bf16 hi/lo planes
    float inv0 = 1.f / l0, inv1 = 1.f / l1;
    const size_t r0 = (size_t)b * TT + tq0;
    const size_t r1 = r0 + 8;
    #pragma unroll
    for (int jd = 0; jd < 8; jd++) {
        int col = h * DH + 8 * jd + 2 * t;
        uint32_t hA, lA, hB, lB;
        split2_bf16(O[jd][0] * inv0, O[jd][1] * inv0, hA, lA);
        split2_bf16(O[jd][2] * inv1, O[jd][3] * inv1, hB, lB);
        *(uint32_t*)&outh[r0 * (HH * DH) + col] = hA;
        *(uint32_t*)&outl[r0 * (HH * DH) + col] = lA;
        *(uint32_t*)&outh[r1 * (HH * DH) + col] = hB;
        *(uint32_t*)&outl[r1 * (HH * DH) + col] = lB;
    }
}

// ---------------------------------------------------------------------------
extern "C" void kernel_launch(void* const* d_in, const int* in_sizes, int n_in,
                              void* d_out, int out_size)
{
    const float* query   = (const float*)d_in[0];
    const float* key_    = (const float*)d_in[1];
    const float* value   = (const float*)d_in[2];
    const float* Wq      = (const float*)d_in[3];
    const float* bq      = (const float*)d_in[4];
    const float* Wk      = (const float*)d_in[5];
    const float* bk      = (const float*)d_in[6];
    const float* Wv      = (const float*)d_in[7];
    const float* bv      = (const float*)d_in[8];
    const float* Wo      = (const float*)d_in[9];
    const float* bo      = (const float*)d_in[10];
    const float* cbias   = (const float*)d_in[11];
    const float* rbias   = (const float*)d_in[12];
    const float* pos_emb = (const float*)d_in[13];

    float *pk;
    cudaGetSymbolAddress((void**)&pk, g_pk);

    __nv_bfloat16 *wqh, *wql, *wkh, *wkl, *wvh, *wvl, *woh, *wol;
    __nv_bfloat16 *xh, *xl, *yh, *yl, *zh, *zl, *ath, *atl;
    __nv_bfloat16 *qph, *qpl, *kp_h, *kp_l, *vp_h, *vp_l;
    cudaGetSymbolAddress((void**)&wqh, g_wq_h); cudaGetSymbolAddress((void**)&wql, g_wq_l);
    cudaGetSymbolAddress((void**)&wkh, g_wk_h); cudaGetSymbolAddress((void**)&wkl, g_wk_l);
    cudaGetSymbolAddress((void**)&wvh, g_wv_h); cudaGetSymbolAddress((void**)&wvl, g_wv_l);
    cudaGetSymbolAddress((void**)&woh, g_wo_h); cudaGetSymbolAddress((void**)&wol, g_wo_l);
    cudaGetSymbolAddress((void**)&xh, g_x_h);   cudaGetSymbolAddress((void**)&xl, g_x_l);
    cudaGetSymbolAddress((void**)&yh, g_y_h);   cudaGetSymbolAddress((void**)&yl, g_y_l);
    cudaGetSymbolAddress((void**)&zh, g_z_h);   cudaGetSymbolAddress((void**)&zl, g_z_l);
    cudaGetSymbolAddress((void**)&ath, g_a_h);  cudaGetSymbolAddress((void**)&atl, g_a_l);
    cudaGetSymbolAddress((void**)&qph, g_qp_h); cudaGetSymbolAddress((void**)&qpl, g_qp_l);
    cudaGetSymbolAddress((void**)&kp_h, g_kp_h); cudaGetSymbolAddress((void**)&kp_l, g_kp_l);
    cudaGetSymbolAddress((void**)&vp_h, g_vp_h); cudaGetSymbolAddress((void**)&vp_l, g_vp_l);

    const int M = BB * TT;     // 4096
    const int N = HH * DH;     // 1024
    const int K = DD;          // 1024

    const int wn4 = DD * HH * DH / 4;      // 262144
    const int an4 = BB * TT * DD / 4;      // 1048576

    // merged packs: 4 weights in one launch, 3 activations in another
    Pack4Args wp;
    wp.src[0] = Wq; wp.hi[0] = wqh; wp.lo[0] = wql;
    wp.src[1] = Wk; wp.hi[1] = wkh; wp.lo[1] = wkl;
    wp.src[2] = Wv; wp.hi[2] = wvh; wp.lo[2] = wvl;
    wp.src[3] = Wo; wp.hi[3] = woh; wp.lo[3] = wol;
    pack_bf16_multi<<<dim3(wn4 / 256, 4), 256>>>(wp, wn4);

    Pack4Args ap;
    ap.src[0] = query; ap.hi[0] = xh; ap.lo[0] = xl;
    ap.src[1] = key_;  ap.hi[1] = yh; ap.lo[1] = yl;
    ap.src[2] = value; ap.hi[2] = zh; ap.lo[2] = zl;
    ap.src[3] = query; ap.hi[3] = xh; ap.lo[3] = xl;   // unused (grid.y=3)
    pack_bf16_multi<<<dim3(an4 / 256, 3), 256>>>(ap, an4);

    // merged QKV projection GEMMs (one launch, grid.z = 3)
    QKVArgs qa;
    qa.Ah[0] = xh; qa.Al[0] = xl; qa.Bh[0] = wqh; qa.Bl[0] = wql;
    qa.bias[0] = bq; qa.oh[0] = qph; qa.ol[0] = qpl;
    qa.Ah[1] = yh; qa.Al[1] = yl; qa.Bh[1] = wkh; qa.Bl[1] = wkl;
    qa.bias[1] = bk; qa.oh[1] = kp_h; qa.ol[1] = kp_l;
    qa.Ah[2] = zh; qa.Al[2] = zl; qa.Bh[2] = wvh; qa.Bl[2] = wvl;
    qa.bias[2] = bv; qa.oh[2] = vp_h; qa.ol[2] = vp_l;

    cudaFuncSetAttribute(gemm_qkv,
                         cudaFuncAttributeMaxDynamicSharedMemorySize, G2_SMEM);
    cudaFuncSetAttribute(gemm_out,
                         cudaFuncAttributeMaxDynamicSharedMemorySize, G2_SMEM);
    gemm_qkv<<<dim3(N / 128, M / 128, 3), 256, G2_SMEM>>>(qa, M, N, K);

    pk_init<<<(NREL * DD + 255) / 256, 256>>>(bk, pk);
    pk_gemm_split<<<dim3(DD / 256, DD / 64), 256>>>(pos_emb, Wk, pk);

    cudaFuncSetAttribute(attn_mma,
                         cudaFuncAttributeMaxDynamicSharedMemorySize, AT_SMEM);
    attn_mma<<<dim3(TT / 64, HH, BB), 128, AT_SMEM>>>(
        qph, qpl, kp_h, kp_l, vp_h, vp_l, pk, cbias, rbias, ath, atl);

    // output projection -> d_out
    gemm_out<<<dim3(N / 128, M / 128), 256, G2_SMEM>>>(
        ath, atl, woh, wol, bo, (float*)d_out, M, N, K);
}